// round 2
// baseline (speedup 1.0000x reference)
#include <cuda_runtime.h>

typedef unsigned long long ull;

#define Bb 32
#define Dd 20
#define Ll 4096
#define Kk 1000
#define Nn (Bb*Ll)            // 131072 points
#define NDLs (Bb*Dd*Ll)       // 2621440 output elems for the tensor
#define SMEM_BYTES ((Kk*Dd + Kk + Kk) * 4)   // emb 80KB + nhalf 4KB + hist 4KB

__device__ float g_kl;
__device__ int   g_hist[Kk];

__device__ __forceinline__ ull pack2(float lo, float hi){
  ull r; asm("mov.b64 %0, {%1, %2};" : "=l"(r) : "f"(lo), "f"(hi)); return r;
}
__device__ __forceinline__ void unpack2(ull v, float& lo, float& hi){
  asm("mov.b64 {%0, %1}, %2;" : "=f"(lo), "=f"(hi) : "l"(v));
}
// Packed dual-FMA: SASS FFMA2 (2x fp32 throughput on sm_100a)
__device__ __forceinline__ ull ffma2(ull a, ull b, ull c){
  ull r; asm("fma.rn.f32x2 %0, %1, %2, %3;" : "=l"(r) : "l"(a), "l"(b), "l"(c)); return r;
}

__global__ void vq_init(){
  int t = blockIdx.x*blockDim.x + threadIdx.x;
  if (t < Kk) g_hist[t] = 0;
  if (t == Kk) g_kl = 0.f;
}

__global__ void __launch_bounds__(256,2) vq_main(const float* __restrict__ x,
                                                 const float* __restrict__ emb,
                                                 float* __restrict__ out){
  extern __shared__ float smem[];
  float* s_emb   = smem;                 // [Kk*Dd]
  float* s_nhalf = smem + Kk*Dd;         // [Kk]  = -0.5*||e_k||^2
  int*   s_hist  = (int*)(s_nhalf + Kk); // [Kk]
  __shared__ float s_wsum[8];

  const int tid = threadIdx.x;

  // cooperative codebook load (80KB) + zero shared histogram
  { const float4* src = (const float4*)emb; float4* dst = (float4*)s_emb;
    for (int i = tid; i < (Kk*Dd)/4; i += 256) dst[i] = src[i]; }
  for (int i = tid; i < Kk; i += 256) s_hist[i] = 0;
  __syncthreads();

  for (int k = tid; k < Kk; k += 256){
    float s = 0.f;
    #pragma unroll
    for (int d = 0; d < Dd; d++){ float v = s_emb[k*Dd+d]; s = fmaf(v, v, s); }
    s_nhalf[k] = -0.5f*s;
  }
  __syncthreads();

  float kl_local = 0.f;
  #pragma unroll 1
  for (int p = 0; p < 2; p++){
    const int n = blockIdx.x*256 + tid + p*(Nn/2);
    const int b = n >> 12, l = n & (Ll-1);
    const float* xb = x + (size_t)b*(Dd*Ll) + l;

    float xv[Dd];
    #pragma unroll
    for (int d = 0; d < Dd; d++) xv[d] = __ldg(xb + d*Ll);
    ull xq[10];
    #pragma unroll
    for (int i = 0; i < 10; i++) xq[i] = pack2(xv[2*i], xv[2*i+1]);

    // argmax_k ( -0.5*||e_k||^2 + x . e_k )  ==  argmin_k dist
    float best = -1e30f; int bk = 0;
    #pragma unroll 2
    for (int k = 0; k < Kk; k++){
      const longlong2* er = (const longlong2*)(s_emb + k*Dd);  // 80B row, 16B aligned
      ull acc = pack2(s_nhalf[k], 0.f);
      #pragma unroll
      for (int i = 0; i < 5; i++){
        longlong2 e = er[i];
        acc = ffma2(xq[2*i],   (ull)e.x, acc);
        acc = ffma2(xq[2*i+1], (ull)e.y, acc);
      }
      float lo, hi; unpack2(acc, lo, hi);
      float s = lo + hi;
      if (s > best){ best = s; bk = k; }   // strict > keeps lowest index on ties (matches argmin)
    }

    // gather code row, write straight-through output (x + (q - x), matching ref rounding)
    float qv[Dd];
    #pragma unroll
    for (int d = 0; d < Dd; d++) qv[d] = s_emb[bk*Dd + d];
    float* ob = out + (size_t)b*(Dd*Ll) + l;
    #pragma unroll
    for (int d = 0; d < Dd; d++) ob[d*Ll] = xv[d] + (qv[d] - xv[d]);

    atomicAdd(&s_hist[bk], 1);

    // KL(t || exp-free form):  sum_d t*(log t - p)
    //   = A/Sx - log Sx - (sum ex*eq)/(Sx*Sq),  with t=ex/Sx, p=eq/Sq
    float mx = xv[0], mq = qv[0];
    #pragma unroll
    for (int d = 1; d < Dd; d++){ mx = fmaxf(mx, xv[d]); mq = fmaxf(mq, qv[d]); }
    float Sx = 0.f, Sq = 0.f, A = 0.f, Cr = 0.f;
    #pragma unroll
    for (int d = 0; d < Dd; d++){
      float xs = xv[d] - mx;
      float ex = __expf(xs);
      float eq = __expf(qv[d] - mq);
      Sx += ex; Sq += eq;
      A  = fmaf(ex, xs, A);
      Cr = fmaf(ex, eq, Cr);
    }
    kl_local += A/Sx - __logf(Sx) - Cr/(Sx*Sq);
  }

  // block-reduce KL partial, one atomic per block
  #pragma unroll
  for (int off = 16; off; off >>= 1)
    kl_local += __shfl_xor_sync(0xFFFFFFFFu, kl_local, off);
  if ((tid & 31) == 0) s_wsum[tid >> 5] = kl_local;
  __syncthreads();
  if (tid == 0){
    float s = 0.f;
    #pragma unroll
    for (int i = 0; i < 8; i++) s += s_wsum[i];
    atomicAdd(&g_kl, s);
  }

  // merge shared histogram into global
  for (int i = tid; i < Kk; i += 256){
    int c = s_hist[i];
    if (c) atomicAdd(&g_hist[i], c);
  }
}

__global__ void vq_fin(float* out, int out_size){
  __shared__ float red[256];
  const int t = threadIdx.x;
  float s = 0.f;
  for (int k = t; k < Kk; k += 256){
    float avg = (float)g_hist[k] * (1.f/(float)Nn);
    s += avg * logf(avg + 1e-10f);
  }
  red[t] = s; __syncthreads();
  for (int off = 128; off; off >>= 1){
    if (t < off) red[t] += red[t+off];
    __syncthreads();
  }
  if (t == 0 && out_size >= NDLs + 2){
    out[NDLs]     = 0.1f * (g_kl / (float)Bb);  // commitment loss
    out[NDLs + 1] = expf(-red[0]);              // perplexity
  }
}

extern "C" void kernel_launch(void* const* d_in, const int* in_sizes, int n_in,
                              void* d_out, int out_size){
  const float* x   = (const float*)d_in[0];   // [32, 20, 4096]
  const float* emb = (const float*)d_in[1];   // [1000, 20]
  float* out = (float*)d_out;

  cudaFuncSetAttribute(vq_main, cudaFuncAttributeMaxDynamicSharedMemorySize, SMEM_BYTES);

  vq_init<<<4, 256>>>();
  vq_main<<<Nn/512, 256, SMEM_BYTES>>>(x, emb, out);  // 256 blocks, 2 points/thread
  vq_fin<<<1, 256>>>(out, out_size);
}

// round 4
// speedup vs baseline: 1.2850x; 1.2850x over previous
#include <cuda_runtime.h>
#include <cstdint>

typedef unsigned long long ull;

#define Bb 32
#define Dd 20
#define Ll 4096
#define Kk 1000
#define Nn (Bb*Ll)              // 131072 points
#define NDLs (Bb*Dd*Ll)
#define ROWF 24                 // floats per smem codebook row (96B)
#define SMEM_BYTES (Kk*ROWF*4)  // 96000 B
#define NPG 1024                // point groups of 128
#define NQ 4                    // codebook quarters (250 codes)
#define NUNITS (NPG*NQ)         // 4096 work units
#define NWARPS (148*8)          // persistent warps
#define FINB (Nn/256)           // 512 fin blocks

__device__ ull   g_pack[Nn];    // (sortable score)<<32 | (2047-idx); 0 = -inf
__device__ int   g_work;
__device__ float g_kl;
__device__ int   g_hist[Kk];
__device__ int   g_done;

__device__ __forceinline__ ull pack2(float lo, float hi){
  ull r; asm("mov.b64 %0, {%1, %2};" : "=l"(r) : "f"(lo), "f"(hi)); return r;
}
__device__ __forceinline__ void unpack2(ull v, float& lo, float& hi){
  asm("mov.b64 {%0, %1}, %2;" : "=f"(lo), "=f"(hi) : "l"(v));
}
__device__ __forceinline__ ull ffma2(ull a, ull b, ull c){
  ull r; asm("fma.rn.f32x2 %0, %1, %2, %3;" : "=l"(r) : "l"(a), "l"(b), "l"(c)); return r;
}
__device__ __forceinline__ ull enc(float s, int idx){
  unsigned u = __float_as_uint(s);
  u = (u & 0x80000000u) ? ~u : (u | 0x80000000u);
  return ((ull)u << 32) | (unsigned)(2047 - idx);
}

__global__ void __launch_bounds__(256,1) vq_main(const float* __restrict__ x,
                                                 const float* __restrict__ emb){
  extern __shared__ float sm[];   // [Kk*24]: e0..e19, nhalf, 0, pad, pad
  const int tid = threadIdx.x, lane = tid & 31;

  for (int k = tid; k < Kk; k += 256){
    const float* e = emb + k*Dd;
    float* r = sm + k*ROWF;
    float s = 0.f;
    #pragma unroll
    for (int d = 0; d < Dd; d++){ float v = __ldg(e + d); r[d] = v; s = fmaf(v, v, s); }
    r[20] = -0.5f*s; r[21] = 0.f; r[22] = 0.f; r[23] = 0.f;
  }
  __syncthreads();

  const int gw = blockIdx.x*8 + (tid >> 5);   // global warp id: static first unit
  int u = gw;
  while (u < NUNITS){
    const int q = u & 3, pg = u >> 2;
    const int k0 = q*250;

    // load 4 points (lane-consecutive -> coalesced), pack into f32x2 pairs
    int nn[4]; ull xq[4][10];
    #pragma unroll
    for (int j = 0; j < 4; j++){
      const int n = pg*128 + 32*j + lane;
      nn[j] = n;
      const float* xp = x + (size_t)(n >> 12)*(Dd*Ll) + (n & (Ll-1));
      float xv[Dd];
      #pragma unroll
      for (int d = 0; d < Dd; d++) xv[d] = __ldg(xp + d*Ll);
      #pragma unroll
      for (int i = 0; i < 10; i++) xq[j][i] = pack2(xv[2*i], xv[2*i+1]);
    }

    float best[4] = {-1e38f,-1e38f,-1e38f,-1e38f};
    int   bk[4]   = {0,0,0,0};

    #pragma unroll 2
    for (int i = 0; i < 250; i++){
      const float* r = sm + (k0 + i)*ROWF;
      const longlong2* rp = (const longlong2*)r;
      longlong2 p0 = rp[0], p1 = rp[1], p2 = rp[2], p3 = rp[3], p4 = rp[4];
      ull init = ((const ull*)r)[10];            // (nhalf, 0)
      #pragma unroll
      for (int j = 0; j < 4; j++){
        ull a = init;
        a = ffma2(xq[j][0], (ull)p0.x, a); a = ffma2(xq[j][1], (ull)p0.y, a);
        a = ffma2(xq[j][2], (ull)p1.x, a); a = ffma2(xq[j][3], (ull)p1.y, a);
        a = ffma2(xq[j][4], (ull)p2.x, a); a = ffma2(xq[j][5], (ull)p2.y, a);
        a = ffma2(xq[j][6], (ull)p3.x, a); a = ffma2(xq[j][7], (ull)p3.y, a);
        a = ffma2(xq[j][8], (ull)p4.x, a); a = ffma2(xq[j][9], (ull)p4.y, a);
        float lo, hi; unpack2(a, lo, hi);
        float s = lo + hi;
        if (s > best[j]){ best[j] = s; bk[j] = k0 + i; }
      }
    }

    #pragma unroll
    for (int j = 0; j < 4; j++)
      atomicMax(&g_pack[nn[j]], enc(best[j], bk[j]));

    // next unit (dynamic, staggered by unit runtime)
    if (lane == 0) u = NWARPS + atomicAdd(&g_work, 1);
    u = __shfl_sync(0xFFFFFFFFu, u, 0);
  }
}

__global__ void __launch_bounds__(256) vq_fin(const float* __restrict__ x,
                                              const float* __restrict__ emb,
                                              float* __restrict__ out, int out_size){
  __shared__ int sh[Kk];
  __shared__ float swr[8];
  __shared__ int slast;
  const int tid = threadIdx.x;
  for (int i = tid; i < Kk; i += 256) sh[i] = 0;
  __syncthreads();

  const int n = blockIdx.x*256 + tid;
  ull pk = g_pack[n];
  g_pack[n] = 0;                                  // reset for next graph replay
  const int code = 2047 - (int)(unsigned)(pk & 0xFFFFFFFFu);

  const int bb = n >> 12, l = n & (Ll-1);
  const float* xp = x + (size_t)bb*(Dd*Ll) + l;
  float xv[Dd], qv[Dd];
  #pragma unroll
  for (int d = 0; d < Dd; d++){ xv[d] = __ldg(xp + d*Ll); qv[d] = __ldg(emb + code*Dd + d); }
  float* op = out + (size_t)bb*(Dd*Ll) + l;
  #pragma unroll
  for (int d = 0; d < Dd; d++) op[d*Ll] = xv[d] + (qv[d] - xv[d]);
  atomicAdd(&sh[code], 1);

  float mx = xv[0], mq = qv[0];
  #pragma unroll
  for (int d = 1; d < Dd; d++){ mx = fmaxf(mx, xv[d]); mq = fmaxf(mq, qv[d]); }
  float Sx = 0.f, Sq = 0.f, A = 0.f, Cr = 0.f;
  #pragma unroll
  for (int d = 0; d < Dd; d++){
    float xs = xv[d] - mx;
    float ex = __expf(xs), eq = __expf(qv[d] - mq);
    Sx += ex; Sq += eq;
    A  = fmaf(ex, xs, A);
    Cr = fmaf(ex, eq, Cr);
  }
  float kl = A/Sx - __logf(Sx) - Cr/(Sx*Sq);

  #pragma unroll
  for (int off = 16; off; off >>= 1) kl += __shfl_xor_sync(0xFFFFFFFFu, kl, off);
  if ((tid & 31) == 0) swr[tid >> 5] = kl;
  __syncthreads();
  if (tid == 0){
    float s = 0.f;
    #pragma unroll
    for (int i = 0; i < 8; i++) s += swr[i];
    atomicAdd(&g_kl, s);
  }
  for (int i = tid; i < Kk; i += 256){ int c = sh[i]; if (c) atomicAdd(&g_hist[i], c); }

  __threadfence();
  __syncthreads();
  if (tid == 0) slast = (atomicAdd(&g_done, 1) == FINB - 1);
  __syncthreads();
  if (slast){
    float s = 0.f;
    for (int k = tid; k < Kk; k += 256){
      float a = (float)(*(volatile int*)&g_hist[k]) * (1.f/(float)Nn);
      s += a * logf(a + 1e-10f);
      g_hist[k] = 0;                              // reset for next replay
    }
    #pragma unroll
    for (int off = 16; off; off >>= 1) s += __shfl_xor_sync(0xFFFFFFFFu, s, off);
    if ((tid & 31) == 0) swr[tid >> 5] = s;
    __syncthreads();
    if (tid == 0){
      float t = 0.f;
      #pragma unroll
      for (int i = 0; i < 8; i++) t += swr[i];
      if (out_size >= NDLs + 2){
        out[NDLs]     = 0.1f * ((*(volatile float*)&g_kl) / (float)Bb);
        out[NDLs + 1] = expf(-t);
      }
      g_kl = 0.f; g_done = 0; g_work = 0;         // reset for next replay
    }
  }
}

extern "C" void kernel_launch(void* const* d_in, const int* in_sizes, int n_in,
                              void* d_out, int out_size){
  const float* x   = (const float*)d_in[0];
  const float* emb = (const float*)d_in[1];
  float* out = (float*)d_out;
  cudaFuncSetAttribute(vq_main, cudaFuncAttributeMaxDynamicSharedMemorySize, SMEM_BYTES);
  vq_main<<<148, 256, SMEM_BYTES>>>(x, emb);
  vq_fin<<<FINB, 256>>>(x, emb, out, out_size);
}